// round 5
// baseline (speedup 1.0000x reference)
#include <cuda_runtime.h>
#include <cuda_bf16.h>

// Scratch accumulators + completion counter (device globals — no allocation).
// Zero-initialized at module load; the finalizing block resets them after each
// replay so every graph replay starts from zero.
__device__ double g_trans_acc;
__device__ double g_rot_acc;
__device__ unsigned g_done;

__device__ __forceinline__ float wrap_angle(float x) {
    // Matches reference: sequential +/- 2*pi correction, fp32 constants.
    const float PI     = 3.14159265358979323846f;  // rounds to fp32(np.pi)
    const float TWO_PI = 6.28318530717958647692f;
    x = (x >  PI) ? x - TWO_PI : x;
    x = (x < -PI) ? x + TWO_PI : x;
    return x;
}

// One component, with loop-invariant per-lane rot flags (predicated, no branches).
#define WMSE_COMP(PC, QC, ISROT)                         \
    do {                                                 \
        float dr_ = (PC) - (QC);                         \
        float dw_ = wrap_angle(PC) - wrap_angle(QC);     \
        if (ISROT) rs = fmaf(dw_, dw_, rs);              \
        else       ts = fmaf(dr_, dr_, ts);              \
    } while (0)

#define WMSE_VEC(P, Q)                                   \
    do {                                                 \
        WMSE_COMP((P).x, (Q).x, rot_x);                  \
        WMSE_COMP((P).y, (Q).y, rot_y);                  \
        WMSE_COMP((P).z, (Q).z, rot_z);                  \
        WMSE_COMP((P).w, (Q).w, rot_w);                  \
    } while (0)

// Coalesced layout: thread t handles vecs t, t+S, t+2S, ... where S = total
// threads and S % 3 == 0 (enforced by the launcher). Vec i covers channels
// (4i)%6 .. (4i)%6+3, so the rot pattern depends only on i%3, which is then
// loop-invariant per thread:
//   r=0: ch 0,1,2,3 -> rot (F,F,F,T)
//   r=1: ch 4,5,0,1 -> rot (T,T,F,F)
//   r=2: ch 2,3,4,5 -> rot (F,T,T,T)
__global__ void __launch_bounds__(256)
wmse_fused_kernel(const float4* __restrict__ pred4,
                  const float4* __restrict__ targ4,
                  long long nvec,
                  const float* __restrict__ pred_s,
                  const float* __restrict__ targ_s,
                  long long tail_begin,
                  long long n_total,
                  float* __restrict__ out,
                  double inv_count) {
    const long long tid = (long long)blockIdx.x * blockDim.x + threadIdx.x;
    const long long S   = (long long)gridDim.x * blockDim.x;  // S % 3 == 0

    const int  r     = (int)(tid % 3);
    const bool rot_x = (r == 1);
    const bool rot_y = (r != 0);
    const bool rot_z = (r == 2);
    const bool rot_w = (r != 1);

    float ts = 0.0f, rs = 0.0f;

    long long i = tid;
    // 4x unrolled: 8 LDG.128 front-batched per iteration (MLP for DRAM latency).
    for (; i + 3 * S < nvec; i += 4 * S) {
        float4 p0 = __ldcs(pred4 + i);
        float4 q0 = __ldcs(targ4 + i);
        float4 p1 = __ldcs(pred4 + i + S);
        float4 q1 = __ldcs(targ4 + i + S);
        float4 p2 = __ldcs(pred4 + i + 2 * S);
        float4 q2 = __ldcs(targ4 + i + 2 * S);
        float4 p3 = __ldcs(pred4 + i + 3 * S);
        float4 q3 = __ldcs(targ4 + i + 3 * S);
        WMSE_VEC(p0, q0);
        WMSE_VEC(p1, q1);
        WMSE_VEC(p2, q2);
        WMSE_VEC(p3, q3);
    }
    for (; i < nvec; i += S) {
        float4 p0 = __ldcs(pred4 + i);
        float4 q0 = __ldcs(targ4 + i);
        WMSE_VEC(p0, q0);
    }

    // Scalar tail (elements beyond nvec*4, if total isn't a multiple of 4).
    for (long long j = tail_begin + tid; j < n_total; j += S) {
        int c = (int)(j % 6);
        float p = pred_s[j], q = targ_s[j];
        if (c >= 3) {
            float d = wrap_angle(p) - wrap_angle(q);
            rs = fmaf(d, d, rs);
        } else {
            float d = p - q;
            ts = fmaf(d, d, ts);
        }
    }

    // Warp reduce.
    #pragma unroll
    for (int o = 16; o > 0; o >>= 1) {
        ts += __shfl_down_sync(0xffffffffu, ts, o);
        rs += __shfl_down_sync(0xffffffffu, rs, o);
    }

    // Block reduce (8 warps @ 256 threads).
    __shared__ float sT[8];
    __shared__ float sR[8];
    const int wid = threadIdx.x >> 5;
    const int lid = threadIdx.x & 31;
    if (lid == 0) { sT[wid] = ts; sR[wid] = rs; }
    __syncthreads();
    if (wid == 0) {
        ts = (lid < 8) ? sT[lid] : 0.0f;
        rs = (lid < 8) ? sR[lid] : 0.0f;
        #pragma unroll
        for (int o = 4; o > 0; o >>= 1) {
            ts += __shfl_down_sync(0xffffffffu, ts, o);
            rs += __shfl_down_sync(0xffffffffu, rs, o);
        }
        if (lid == 0) {
            atomicAdd(&g_trans_acc, (double)ts);
            atomicAdd(&g_rot_acc,   (double)rs);
        }
    }

    // Last-block-done finalize: one block writes the output and resets state.
    __shared__ bool amLast;
    if (threadIdx.x == 0) {
        __threadfence();  // make this block's atomicAdds visible before arrival
        unsigned prev = atomicAdd(&g_done, 1u);
        amLast = (prev == gridDim.x - 1);
    }
    __syncthreads();
    if (amLast && threadIdx.x == 0) {
        __threadfence();  // order: all blocks' accumulator adds -> our reads
        double t  = g_trans_acc * inv_count * 1.0;    // TRANS_WEIGHT
        double r2 = g_rot_acc   * inv_count * 100.0;  // ROT_WEIGHT
        out[0] = (float)(t + r2);  // total_loss
        out[1] = (float)t;         // trans_loss
        out[2] = (float)r2;        // rot_loss
        // Reset for the next graph replay.
        g_trans_acc = 0.0;
        g_rot_acc   = 0.0;
        g_done      = 0u;
    }
}

extern "C" void kernel_launch(void* const* d_in, const int* in_sizes, int n_in,
                              void* d_out, int out_size) {
    const float* pred = (const float*)d_in[0];
    const float* targ = (const float*)d_in[1];
    float* out = (float*)d_out;

    const long long n = (long long)in_sizes[0];   // B*T*6 total elements
    const long long nvec = n / 4;                 // float4 count
    const long long tail_begin = nvec * 4;
    const double inv_count = 1.0 / (double)(n / 2);

    const int threads = 256;
    // 256 % 3 == 1, so blocks must be a multiple of 3 for S % 3 == 0.
    int blocks = 1182;  // ~8 CTAs/SM on 148 SMs, divisible by 3
    long long max_useful = (nvec + threads - 1) / threads;
    if (max_useful < (long long)blocks) {
        blocks = (int)max_useful;
        blocks -= blocks % 3;       // preserve S % 3 == 0
        if (blocks < 3) blocks = 3;
    }

    wmse_fused_kernel<<<blocks, threads>>>(
        (const float4*)pred, (const float4*)targ, nvec,
        pred, targ, tail_begin, n, out, inv_count);
}